// round 14
// baseline (speedup 1.0000x reference)
#include <cuda_runtime.h>
#include <cuda_bf16.h>
#include <math.h>
#include <stdint.h>

#define NN 4096
#define KK 32
#define CC 128
#define VV 21
#define NTILE 1024          // NN/4 tiles of 128 rows
#define GRID 296            // 2 CTAs per SM exactly

// ---------------- precomputed tensors (device globals) ----------------
__device__ float g_base[CC];
__device__ float g_u0[CC];
__device__ __nv_bfloat16 g_Tb[VV * CC];
__device__ float g_TW[VV][VV];
__device__ float g_g0[VV];
__device__ float g_g1[VV];
__device__ float g_key[NN];
__device__ __align__(16) __nv_bfloat16 g_Bb[CC * CC]; // bf16(We2) [k][n]

// ---------------- PTX helpers (plain sm_103-legal only) ----------------
__device__ __forceinline__ uint32_t smem_u32(const void* p) {
    uint32_t a;
    asm("{ .reg .u64 t; cvta.to.shared.u64 t, %1; cvt.u32.u64 %0, t; }" : "=r"(a) : "l"(p));
    return a;
}
__device__ __forceinline__ void ldmx4(uint32_t* r, uint32_t p) {
    asm volatile("ldmatrix.sync.aligned.m8n8.x4.shared.b16 {%0,%1,%2,%3}, [%4];"
                 : "=r"(r[0]), "=r"(r[1]), "=r"(r[2]), "=r"(r[3]) : "r"(p));
}
__device__ __forceinline__ void ldmx4t(uint32_t* r, uint32_t p) {
    asm volatile("ldmatrix.sync.aligned.m8n8.x4.trans.shared.b16 {%0,%1,%2,%3}, [%4];"
                 : "=r"(r[0]), "=r"(r[1]), "=r"(r[2]), "=r"(r[3]) : "r"(p));
}
__device__ __forceinline__ void mma16816(float* d, const uint32_t* a, uint32_t b0, uint32_t b1) {
    asm volatile(
        "mma.sync.aligned.m16n8k16.row.col.f32.bf16.bf16.f32 "
        "{%0,%1,%2,%3}, {%4,%5,%6,%7}, {%8,%9}, {%0,%1,%2,%3};"
        : "+f"(d[0]), "+f"(d[1]), "+f"(d[2]), "+f"(d[3])
        : "r"(a[0]), "r"(a[1]), "r"(a[2]), "r"(a[3]), "r"(b0), "r"(b1));
}
__device__ __forceinline__ void bar_sync(int id, int cnt) {
    asm volatile("bar.sync %0, %1;" :: "r"(id), "r"(cnt) : "memory");
}
__device__ __forceinline__ void bar_arrive(int id, int cnt) {
    asm volatile("bar.arrive %0, %1;" :: "r"(id), "r"(cnt) : "memory");
}

// ---------------- precompute kernel (grid=32, block=256) ----------------
__global__ void precompute_kernel(
    const float* __restrict__ bl1, const float* __restrict__ bo1,
    const float* __restrict__ Wl2, const float* __restrict__ bl2,
    const float* __restrict__ Wr2, const float* __restrict__ br2,
    const float* __restrict__ be2, const float* __restrict__ bo2,
    const float* __restrict__ We2,
    const float* __restrict__ W_s, const float* __restrict__ W_out,
    const float* __restrict__ b_out,
    const float* __restrict__ mask, const float* __restrict__ chain_M,
    const float* __restrict__ z)
{
    __shared__ float sh0[CC];
    __shared__ float sh1[CC];
    __shared__ float sh2[CC];
    const int b = blockIdx.x;
    const int t = threadIdx.x;

    {
        int i = b * 256 + t;
        if (i < NN) {
            float cm = __fadd_rn(__fmul_rn(chain_M[i], mask[i]), 1e-4f);
            g_key[i] = __fmul_rn(cm, fabsf(z[i]));
        }
    }
    for (int i = b * 256 + t; i < CC * CC; i += 32 * 256)
        g_Bb[i] = __float2bfloat16(We2[i]);

    if (b < VV) {
        if (t < CC) {
            float acc = 0.f;
            for (int hh = 0; hh < CC; hh++)
                acc += W_s[b * CC + hh] * Wl2[(CC + hh) * CC + t];
            g_Tb[b * CC + t] = __float2bfloat16(acc);
            sh0[t] = acc;
        }
        __syncthreads();
        if (t < VV) {
            float acc = 0.f;
            for (int c = 0; c < CC; c++)
                acc += sh0[c] * W_out[c * VV + t];
            g_TW[b][t] = acc;
        }
    } else if (b == VV) {
        if (t < CC) sh0[t] = bl1[t] + bo1[t];          // c0
        __syncthreads();
        if (t < CC) {
            float u = 0.f, r = 0.f;
            for (int d = 0; d < CC; d++) {
                float c0 = sh0[d];
                u += c0 * Wl2[d * CC + t];
                r += c0 * Wr2[d * CC + t];
            }
            sh1[t] = u;  g_u0[t] = u;
            g_base[t] = bl2[t] + r + br2[t] + be2[t];
            sh2[t] = bl2[t] + bo2[t];
        }
        __syncthreads();
        if (t < VV) {
            float a0 = b_out[t], a1 = 0.f;
            for (int c = 0; c < CC; c++) {
                float wo = W_out[c * VV + t];
                a0 += sh2[c] * wo;
                a1 += sh1[c] * wo;
            }
            g_g0[t] = a0;
            g_g1[t] = a1;
        }
    }
}

// ---------------- main kernel smem ----------------
// A/B layout: 256B rows, 16B chunk j stored at j ^ (row & 7) -> ldmatrix
// conflict-free, no padding.
struct TileBuf {
    __nv_bfloat16 A[CC * CC];   // 32 KB swizzled E tile
    float BB[4][CC];            // base + mk*u0 per node (producer-computed)
    float Am[4][KK];
    int   Sv[4][KK];
    float Wv[4][VV];
    float Mk[4];
};
struct Smem {
    __nv_bfloat16 B[CC * CC];   // 32 KB swizzled We2
    TileBuf buf[2];
    __nv_bfloat16 T2[VV * CC];  // bf16 T table
    float Base[CC], U0[CC], A2[CC];
    float G0[24], G1[24];
    float TW[VV][VV];
    float Sc2[2][4][KK][2];     // [parity][node][k][n-half]
};

// barrier ids: 1+p = FULL[p], 3+p = EMPTY[p], 5+h = pair(h) sync
#define BAR_FULL  1
#define BAR_EMPTY 3
#define BAR_PAIR  5

// ---------------- main fused kernel ----------------
// 320 threads: warps 0-7 consumers (GEMM+epilogue), warps 8-9 producers.
// Consumer warp grid 4m x 2n: h = wid>>1 (node, rows h*32..h*32+31),
// wcol = wid&1 (channels wcol*64..wcol*64+63). Warp tile 32x64, acc[64]:
// acc[(mt*8 + nblk)*4 + j], mt in {0,1} (rows mt*16+gid, +8),
// nblk in {0..7} (cols wcol*64 + nblk*8 + qid*2, +1).
__global__ void __launch_bounds__(320, 2) gat_mma_kernel(
    const float* __restrict__ E,
    const int*   __restrict__ E_idx,
    const int*   __restrict__ S,
    const float* __restrict__ mask,
    const float* __restrict__ a2,
    float*       __restrict__ out)
{
    extern __shared__ char raw[];
    Smem* sm = (Smem*)raw;

    const int t    = threadIdx.x;
    const int lane = t & 31;
    const int wid  = t >> 5;
    const int b    = blockIdx.x;
    const int niter = (NTILE - b + GRID - 1) / GRID;

    // ---- one-time setup: B + tables (all 320 threads) ----
    {
        const uint4* Bg = (const uint4*)g_Bb;
        for (int i = t; i < 2048; i += 320) {
            int r = i >> 4, j = i & 15;
            *(uint4*)((char*)sm->B + r * 256 + ((j ^ (r & 7)) << 4)) = Bg[i];
        }
        for (int i = t; i < VV * CC; i += 320) sm->T2[i] = g_Tb[i];
        if (t < CC) {
            sm->Base[t] = g_base[t];
            sm->U0[t]   = g_u0[t];
            sm->A2[t]   = a2[t];
        }
        if (t < VV) { sm->G0[t] = g_g0[t]; sm->G1[t] = g_g1[t]; }
        for (int i = t; i < VV * VV; i += 320)
            sm->TW[i / VV][i % VV] = g_TW[i / VV][i % VV];
    }
    __syncthreads();

    if (wid < 8) {
        // =========================== CONSUMERS ===========================
        const int h    = wid >> 1;      // node 0..3
        const int wcol = wid & 1;       // n-half 0..1

        const int arow0 = h * 32 + (lane & 15);
        const int arow1 = arow0 + 16;
        const uint32_t Aoff0 = (uint32_t)arow0 * 256;
        const uint32_t Aoff1 = (uint32_t)arow1 * 256;
        const int rm0 = arow0 & 7, rm1 = arow1 & 7;
        const int ahi = lane >> 4;
        const int bsub = lane >> 3;
        const int rlow = (bsub & 1) * 8 + (lane & 7);
        const int rb7  = rlow & 7;
        const int bhi  = bsub >> 1;
        const int pg   = wcol * 8;
        const uint32_t bAddr = smem_u32(sm->B) + rlow * 256;

        for (int it = 0; it < niter; it++) {
            const int tile = b + it * GRID;
            const int p = it & 1;
            bar_sync(BAR_FULL + p, 320);
            TileBuf* tb = &sm->buf[p];
            const uint32_t Ab0 = smem_u32(tb->A) + Aoff0;
            const uint32_t Ab1 = smem_u32(tb->A) + Aoff1;

            float acc[64];
            #pragma unroll
            for (int i = 0; i < 64; i++) acc[i] = 0.f;

            #pragma unroll
            for (int ks = 0; ks < 8; ks++) {
                uint32_t af0[4], af1[4];
                ldmx4(af0, Ab0 + (((ks * 2 + ahi) ^ rm0) << 4));
                ldmx4(af1, Ab1 + (((ks * 2 + ahi) ^ rm1) << 4));
                #pragma unroll
                for (int pp = 0; pp < 4; pp++) {
                    uint32_t bf[4];
                    ldmx4t(bf, bAddr + ks * 4096 + (((pg + pp * 2 + bhi) ^ rb7) << 4));
                    const int n0 = pp * 2;
                    mma16816(&acc[(0 * 8 + n0)     * 4], af0, bf[0], bf[1]);
                    mma16816(&acc[(0 * 8 + n0 + 1) * 4], af0, bf[2], bf[3]);
                    mma16816(&acc[(1 * 8 + n0)     * 4], af1, bf[0], bf[1]);
                    mma16816(&acc[(1 * 8 + n0 + 1) * 4], af1, bf[2], bf[3]);
                }
            }

            // ---- partial scores over this warp's 64 channels ----
            {
                const int gid = lane >> 2;
                const int qid = lane & 3;
                #pragma unroll
                for (int mt = 0; mt < 2; mt++) {
                    const int klo = mt * 16 + gid;
                    const int khi = klo + 8;
                    const float aA_lo = tb->Am[h][klo];
                    const float aA_hi = tb->Am[h][khi];
                    const __nv_bfloat162* Tlo =
                        (const __nv_bfloat162*)&sm->T2[tb->Sv[h][klo] * CC];
                    const __nv_bfloat162* Thi =
                        (const __nv_bfloat162*)&sm->T2[tb->Sv[h][khi] * CC];

                    float s_lo = 0.f, s_hi = 0.f;
                    #pragma unroll
                    for (int nblk = 0; nblk < 8; nblk++) {
                        const int c0 = wcol * 64 + nblk * 8 + qid * 2;
                        const float2 bb = *(const float2*)&tb->BB[h][c0];
                        const float2 aa = *(const float2*)&sm->A2[c0];
                        const float2 tl = __bfloat1622float2(Tlo[c0 >> 1]);
                        const float2 th = __bfloat1622float2(Thi[c0 >> 1]);
                        const float* d = &acc[(mt * 8 + nblk) * 4];

                        float p0 = d[0] + bb.x + aA_lo * tl.x;   // (klo, c0)
                        float p1 = d[1] + bb.y + aA_lo * tl.y;   // (klo, c0+1)
                        float p2 = d[2] + bb.x + aA_hi * th.x;   // (khi, c0)
                        float p3 = d[3] + bb.y + aA_hi * th.y;   // (khi, c0+1)
                        p0 = fmaxf(p0, 0.2f * p0);
                        p1 = fmaxf(p1, 0.2f * p1);
                        p2 = fmaxf(p2, 0.2f * p2);
                        p3 = fmaxf(p3, 0.2f * p3);
                        s_lo = fmaf(p0, aa.x, s_lo);
                        s_lo = fmaf(p1, aa.y, s_lo);
                        s_hi = fmaf(p2, aa.x, s_hi);
                        s_hi = fmaf(p3, aa.y, s_hi);
                    }
                    s_lo += __shfl_xor_sync(0xffffffffu, s_lo, 1);
                    s_lo += __shfl_xor_sync(0xffffffffu, s_lo, 2);
                    s_hi += __shfl_xor_sync(0xffffffffu, s_hi, 1);
                    s_hi += __shfl_xor_sync(0xffffffffu, s_hi, 2);
                    if (qid == 0) {
                        sm->Sc2[p][h][klo][wcol] = s_lo;
                        sm->Sc2[p][h][khi][wcol] = s_hi;
                    }
                }
            }
            // pair-local sync: both warps of node h (64 threads)
            bar_sync(BAR_PAIR + h, 64);

            // ---- softmax over k + 21-bin logits + log_softmax (even warp) ----
            if (wcol == 0) {
                const int n = tile * 4 + h;
                const float aA = tb->Am[h][lane];
                const int   sk = tb->Sv[h][lane];

                float score = sm->Sc2[p][h][lane][0] + sm->Sc2[p][h][lane][1];
                float mx = score;
                #pragma unroll
                for (int o = 16; o > 0; o >>= 1)
                    mx = fmaxf(mx, __shfl_xor_sync(0xffffffffu, mx, o));
                float e = expf(score - mx);
                float ssum = e;
                #pragma unroll
                for (int o = 16; o > 0; o >>= 1)
                    ssum += __shfl_xor_sync(0xffffffffu, ssum, o);
                atomicAdd(&tb->Wv[h][sk], (e / ssum) * aA);
                __syncwarp();

                float lg = -1e30f;
                if (lane < VV) {
                    lg = sm->G0[lane] + tb->Mk[h] * sm->G1[lane];
                    #pragma unroll
                    for (int u = 0; u < VV; u++)
                        lg = fmaf(tb->Wv[h][u], sm->TW[u][lane], lg);
                }
                float mx2 = lg;
                #pragma unroll
                for (int o = 16; o > 0; o >>= 1)
                    mx2 = fmaxf(mx2, __shfl_xor_sync(0xffffffffu, mx2, o));
                float e2 = (lane < VV) ? expf(lg - mx2) : 0.f;
                float s2 = e2;
                #pragma unroll
                for (int o = 16; o > 0; o >>= 1)
                    s2 += __shfl_xor_sync(0xffffffffu, s2, o);
                if (lane < VV)
                    out[n * VV + lane] = lg - mx2 - logf(s2);
            }
            bar_arrive(BAR_EMPTY + p, 320);
        }
    } else {
        // =========================== PRODUCERS ===========================
        const int tp = t - 256;                     // 0..63
        for (int it = 0; it < niter; it++) {
            const int tile = b + it * GRID;
            const int p = it & 1;
            if (it >= 2) bar_sync(BAR_EMPTY + p, 320);
            TileBuf* tb = &sm->buf[p];

            // E tile: 4096 float4 loads, cvt bf16, swizzled STS
            const float4* Eg = (const float4*)(E + (size_t)tile * (CC * CC));
            char* Ab = (char*)tb->A;
            #pragma unroll 16
            for (int s = 0; s < 64; s++) {
                const int i = tp + (s << 6);
                float4 v = Eg[i];
                const int r = i >> 5, q = i & 31;
                __nv_bfloat162 lo = __float22bfloat162_rn(make_float2(v.x, v.y));
                __nv_bfloat162 hi = __float22bfloat162_rn(make_float2(v.z, v.w));
                uint2 pk;
                pk.x = *(const uint32_t*)&lo;
                pk.y = *(const uint32_t*)&hi;
                *(uint2*)(Ab + r * 256 + (((q >> 1) ^ (r & 7)) << 4) + (q & 1) * 8) = pk;
            }
            // metadata
            #pragma unroll
            for (int i = tp; i < 128; i += 64) {
                const int hh = i >> 5, k = i & 31;
                const int n = tile * 4 + hh;
                const int j = E_idx[n * KK + k];
                tb->Sv[hh][k] = S[j];
                float kn = g_key[n], kj = g_key[j];
                float att = (kn > kj || (kn == kj && n > j)) ? 1.f : 0.f;
                tb->Am[hh][k] = mask[n] * att;
            }
            if (tp < 4) tb->Mk[tp] = mask[tile * 4 + tp];
            // BB[h][c] = Base[c] + mask_n * U0[c]
            #pragma unroll
            for (int i = tp; i < 4 * CC; i += 64) {
                const int hh = i >> 7, c = i & 127;
                tb->BB[hh][c] = sm->Base[c] + mask[tile * 4 + hh] * sm->U0[c];
            }
            for (int i = tp; i < 4 * VV; i += 64) tb->Wv[i / VV][i % VV] = 0.f;

            bar_arrive(BAR_FULL + p, 320);
        }
    }
}

// ---------------- launch ----------------
extern "C" void kernel_launch(void* const* d_in, const int* in_sizes, int n_in,
                              void* d_out, int out_size)
{
    const float* E       = (const float*)d_in[0];
    const int*   E_idx   = (const int*)  d_in[1];
    const int*   S       = (const int*)  d_in[2];
    const float* mask    = (const float*)d_in[3];
    const float* chain_M = (const float*)d_in[4];
    const float* z       = (const float*)d_in[5];
    const float* bl1     = (const float*)d_in[7];
    const float* bo1     = (const float*)d_in[13];
    const float* Wl2     = (const float*)d_in[14];
    const float* bl2     = (const float*)d_in[15];
    const float* Wr2     = (const float*)d_in[16];
    const float* br2     = (const float*)d_in[17];
    const float* We2     = (const float*)d_in[18];
    const float* be2     = (const float*)d_in[19];
    const float* a2      = (const float*)d_in[20];
    const float* bo2     = (const float*)d_in[21];
    const float* W_s     = (const float*)d_in[22];
    const float* W_out   = (const float*)d_in[23];
    const float* b_out   = (const float*)d_in[24];

    float* out = (float*)d_out;

    const int smem_bytes = (int)sizeof(Smem);
    cudaFuncSetAttribute(gat_mma_kernel,
                         cudaFuncAttributeMaxDynamicSharedMemorySize, smem_bytes);

    precompute_kernel<<<32, 256>>>(bl1, bo1, Wl2, bl2, Wr2, br2, be2, bo2, We2,
                                   W_s, W_out, b_out, mask, chain_M, z);
    gat_mma_kernel<<<GRID, 320, smem_bytes>>>(E, E_idx, S, mask, a2, out);
}

// round 15
// speedup vs baseline: 1.2917x; 1.2917x over previous
#include <cuda_runtime.h>
#include <cuda_bf16.h>
#include <math.h>
#include <stdint.h>

#define NN 4096
#define KK 32
#define CC 128
#define VV 21
#define NTILE 1024          // NN/4 tiles of 128 rows
#define GRID 296            // 2 CTAs per SM exactly

// ---------------- precomputed tensors (device globals) ----------------
__device__ float g_base[CC];
__device__ float g_u0[CC];
__device__ __nv_bfloat16 g_Tb[VV * CC];
__device__ float g_TW[VV][VV];
__device__ float g_g0[VV];
__device__ float g_g1[VV];
__device__ float g_key[NN];
__device__ __align__(16) __nv_bfloat16 g_Bb[CC * CC]; // bf16(We2) [k][n]

// ---------------- PTX helpers (plain sm_103-legal only) ----------------
__device__ __forceinline__ uint32_t smem_u32(const void* p) {
    uint32_t a;
    asm("{ .reg .u64 t; cvta.to.shared.u64 t, %1; cvt.u32.u64 %0, t; }" : "=r"(a) : "l"(p));
    return a;
}
__device__ __forceinline__ void ldmx4(uint32_t* r, uint32_t p) {
    asm volatile("ldmatrix.sync.aligned.m8n8.x4.shared.b16 {%0,%1,%2,%3}, [%4];"
                 : "=r"(r[0]), "=r"(r[1]), "=r"(r[2]), "=r"(r[3]) : "r"(p));
}
__device__ __forceinline__ void ldmx4t(uint32_t* r, uint32_t p) {
    asm volatile("ldmatrix.sync.aligned.m8n8.x4.trans.shared.b16 {%0,%1,%2,%3}, [%4];"
                 : "=r"(r[0]), "=r"(r[1]), "=r"(r[2]), "=r"(r[3]) : "r"(p));
}
__device__ __forceinline__ void mma16816(float* d, const uint32_t* a, uint32_t b0, uint32_t b1) {
    asm volatile(
        "mma.sync.aligned.m16n8k16.row.col.f32.bf16.bf16.f32 "
        "{%0,%1,%2,%3}, {%4,%5,%6,%7}, {%8,%9}, {%0,%1,%2,%3};"
        : "+f"(d[0]), "+f"(d[1]), "+f"(d[2]), "+f"(d[3])
        : "r"(a[0]), "r"(a[1]), "r"(a[2]), "r"(a[3]), "r"(b0), "r"(b1));
}
__device__ __forceinline__ void bar_sync(int id, int cnt) {
    asm volatile("bar.sync %0, %1;" :: "r"(id), "r"(cnt) : "memory");
}
__device__ __forceinline__ void bar_arrive(int id, int cnt) {
    asm volatile("bar.arrive %0, %1;" :: "r"(id), "r"(cnt) : "memory");
}

// ---------------- precompute kernel (grid=32, block=256) ----------------
__global__ void precompute_kernel(
    const float* __restrict__ bl1, const float* __restrict__ bo1,
    const float* __restrict__ Wl2, const float* __restrict__ bl2,
    const float* __restrict__ Wr2, const float* __restrict__ br2,
    const float* __restrict__ be2, const float* __restrict__ bo2,
    const float* __restrict__ We2,
    const float* __restrict__ W_s, const float* __restrict__ W_out,
    const float* __restrict__ b_out,
    const float* __restrict__ mask, const float* __restrict__ chain_M,
    const float* __restrict__ z)
{
    __shared__ float sh0[CC];
    __shared__ float sh1[CC];
    __shared__ float sh2[CC];
    const int b = blockIdx.x;
    const int t = threadIdx.x;

    {
        int i = b * 256 + t;
        if (i < NN) {
            float cm = __fadd_rn(__fmul_rn(chain_M[i], mask[i]), 1e-4f);
            g_key[i] = __fmul_rn(cm, fabsf(z[i]));
        }
    }
    for (int i = b * 256 + t; i < CC * CC; i += 32 * 256)
        g_Bb[i] = __float2bfloat16(We2[i]);

    if (b < VV) {
        if (t < CC) {
            float acc = 0.f;
            for (int hh = 0; hh < CC; hh++)
                acc += W_s[b * CC + hh] * Wl2[(CC + hh) * CC + t];
            g_Tb[b * CC + t] = __float2bfloat16(acc);
            sh0[t] = acc;
        }
        __syncthreads();
        if (t < VV) {
            float acc = 0.f;
            for (int c = 0; c < CC; c++)
                acc += sh0[c] * W_out[c * VV + t];
            g_TW[b][t] = acc;
        }
    } else if (b == VV) {
        if (t < CC) sh0[t] = bl1[t] + bo1[t];          // c0
        __syncthreads();
        if (t < CC) {
            float u = 0.f, r = 0.f;
            for (int d = 0; d < CC; d++) {
                float c0 = sh0[d];
                u += c0 * Wl2[d * CC + t];
                r += c0 * Wr2[d * CC + t];
            }
            sh1[t] = u;  g_u0[t] = u;
            g_base[t] = bl2[t] + r + br2[t] + be2[t];
            sh2[t] = bl2[t] + bo2[t];
        }
        __syncthreads();
        if (t < VV) {
            float a0 = b_out[t], a1 = 0.f;
            for (int c = 0; c < CC; c++) {
                float wo = W_out[c * VV + t];
                a0 += sh2[c] * wo;
                a1 += sh1[c] * wo;
            }
            g_g0[t] = a0;
            g_g1[t] = a1;
        }
    }
}

// ---------------- main kernel smem ----------------
// A/B layout: 256B rows, 16B chunk j stored at j ^ (row & 7) -> ldmatrix
// conflict-free, no padding. sizeof(Smem) MUST stay <= 112 KB so that the
// 8 KB-granularity smem allocation leaves room for 2 CTAs/SM.
struct TileBuf {
    __nv_bfloat16 A[CC * CC];   // 32 KB swizzled E tile
    float Am[4][KK];
    int   Sv[4][KK];
    float Wv[4][VV];
    float Mk[4];
};
struct Smem {
    __nv_bfloat16 B[CC * CC];   // 32 KB swizzled We2
    TileBuf buf[2];
    __nv_bfloat16 T2[VV * CC];  // bf16 T table
    float Base[CC], U0[CC], A2[CC];
    float G0[24], G1[24];
    float TW[VV][VV];
    float Sc2[4][KK][2];        // per-node per-k partials (2 n-half warps)
};

// barrier ids: 1+p = FULL[p] (320), 3+p = EMPTY[p] (320),
// 5+h = pair(h) (64), 9+p = HALF[p] (192: 2 producer warps + 4 h01 warps)
#define BAR_FULL  1
#define BAR_EMPTY 3
#define BAR_PAIR  5
#define BAR_HALF  9

// ---------------- main fused kernel ----------------
// 320 threads: warps 0-7 consumers, warps 8-9 producers.
// Consumer warp grid 4m x 2n: h = wid>>1 (node, rows h*32..h*32+31),
// wcol = wid&1 (channels wcol*64..+63). Warp tile 32x64, acc[64]:
// acc[(mt*8 + nblk)*4 + j], mt in {0,1} (rows mt*16+gid, +8),
// nblk in {0..7} (cols wcol*64 + nblk*8 + qid*2, +1).
// Nodes 0-1 (rows 0-63) start their GEMM at HALF; everyone joins FULL
// before the metadata-dependent score phase (counting barrier: arrival
// order is irrelevant, 320 arrivals per parity per iteration).
__global__ void __launch_bounds__(320, 2) gat_mma_kernel(
    const float* __restrict__ E,
    const int*   __restrict__ E_idx,
    const int*   __restrict__ S,
    const float* __restrict__ mask,
    const float* __restrict__ a2,
    float*       __restrict__ out)
{
    extern __shared__ char raw[];
    Smem* sm = (Smem*)raw;

    const int t    = threadIdx.x;
    const int lane = t & 31;
    const int wid  = t >> 5;
    const int b    = blockIdx.x;
    const int niter = (NTILE - b + GRID - 1) / GRID;

    // ---- one-time setup: B + tables (all 320 threads) ----
    {
        const uint4* Bg = (const uint4*)g_Bb;
        for (int i = t; i < 2048; i += 320) {
            int r = i >> 4, j = i & 15;
            *(uint4*)((char*)sm->B + r * 256 + ((j ^ (r & 7)) << 4)) = Bg[i];
        }
        for (int i = t; i < VV * CC; i += 320) sm->T2[i] = g_Tb[i];
        if (t < CC) {
            sm->Base[t] = g_base[t];
            sm->U0[t]   = g_u0[t];
            sm->A2[t]   = a2[t];
        }
        if (t < VV) { sm->G0[t] = g_g0[t]; sm->G1[t] = g_g1[t]; }
        for (int i = t; i < VV * VV; i += 320)
            sm->TW[i / VV][i % VV] = g_TW[i / VV][i % VV];
    }
    __syncthreads();

    if (wid < 8) {
        // =========================== CONSUMERS ===========================
        const int h    = wid >> 1;      // node 0..3
        const int wcol = wid & 1;       // n-half 0..1
        const bool early = (h < 2);     // rows 0-63 -> can start at HALF

        const int arow0 = h * 32 + (lane & 15);
        const int arow1 = arow0 + 16;
        const uint32_t Aoff0 = (uint32_t)arow0 * 256;
        const uint32_t Aoff1 = (uint32_t)arow1 * 256;
        const int rm0 = arow0 & 7, rm1 = arow1 & 7;
        const int ahi = lane >> 4;
        const int bsub = lane >> 3;
        const int rlow = (bsub & 1) * 8 + (lane & 7);
        const int rb7  = rlow & 7;
        const int bhi  = bsub >> 1;
        const int pg   = wcol * 8;
        const uint32_t bAddr = smem_u32(sm->B) + rlow * 256;

        for (int it = 0; it < niter; it++) {
            const int tile = b + it * GRID;
            const int p = it & 1;

            if (early) bar_sync(BAR_HALF + p, 192);   // rows 0-63 ready
            else       bar_sync(BAR_FULL + p, 320);   // whole tile ready
            TileBuf* tb = &sm->buf[p];
            const uint32_t Ab0 = smem_u32(tb->A) + Aoff0;
            const uint32_t Ab1 = smem_u32(tb->A) + Aoff1;

            float acc[64];
            #pragma unroll
            for (int i = 0; i < 64; i++) acc[i] = 0.f;

            #pragma unroll
            for (int ks = 0; ks < 8; ks++) {
                uint32_t af0[4], af1[4];
                ldmx4(af0, Ab0 + (((ks * 2 + ahi) ^ rm0) << 4));
                ldmx4(af1, Ab1 + (((ks * 2 + ahi) ^ rm1) << 4));
                #pragma unroll
                for (int pp = 0; pp < 4; pp++) {
                    uint32_t bf[4];
                    ldmx4t(bf, bAddr + ks * 4096 + (((pg + pp * 2 + bhi) ^ rb7) << 4));
                    const int n0 = pp * 2;
                    mma16816(&acc[(0 * 8 + n0)     * 4], af0, bf[0], bf[1]);
                    mma16816(&acc[(0 * 8 + n0 + 1) * 4], af0, bf[2], bf[3]);
                    mma16816(&acc[(1 * 8 + n0)     * 4], af1, bf[0], bf[1]);
                    mma16816(&acc[(1 * 8 + n0 + 1) * 4], af1, bf[2], bf[3]);
                }
            }

            if (early) bar_sync(BAR_FULL + p, 320);   // metadata now ready

            // ---- partial scores over this warp's 64 channels ----
            {
                const int gid = lane >> 2;
                const int qid = lane & 3;
                const float mk = tb->Mk[h];
                #pragma unroll
                for (int mt = 0; mt < 2; mt++) {
                    const int klo = mt * 16 + gid;
                    const int khi = klo + 8;
                    const float aA_lo = tb->Am[h][klo];
                    const float aA_hi = tb->Am[h][khi];
                    const __nv_bfloat162* Tlo =
                        (const __nv_bfloat162*)&sm->T2[tb->Sv[h][klo] * CC];
                    const __nv_bfloat162* Thi =
                        (const __nv_bfloat162*)&sm->T2[tb->Sv[h][khi] * CC];

                    float s_lo = 0.f, s_hi = 0.f;
                    #pragma unroll
                    for (int nblk = 0; nblk < 8; nblk++) {
                        const int c0 = wcol * 64 + nblk * 8 + qid * 2;
                        const float2 ba = *(const float2*)&sm->Base[c0];
                        const float2 u0 = *(const float2*)&sm->U0[c0];
                        const float2 aa = *(const float2*)&sm->A2[c0];
                        const float2 tl = __bfloat1622float2(Tlo[c0 >> 1]);
                        const float2 th = __bfloat1622float2(Thi[c0 >> 1]);
                        const float bb0 = ba.x + mk * u0.x;
                        const float bb1 = ba.y + mk * u0.y;
                        const float* d = &acc[(mt * 8 + nblk) * 4];

                        float p0 = d[0] + bb0 + aA_lo * tl.x;   // (klo, c0)
                        float p1 = d[1] + bb1 + aA_lo * tl.y;   // (klo, c0+1)
                        float p2 = d[2] + bb0 + aA_hi * th.x;   // (khi, c0)
                        float p3 = d[3] + bb1 + aA_hi * th.y;   // (khi, c0+1)
                        p0 = fmaxf(p0, 0.2f * p0);
                        p1 = fmaxf(p1, 0.2f * p1);
                        p2 = fmaxf(p2, 0.2f * p2);
                        p3 = fmaxf(p3, 0.2f * p3);
                        s_lo = fmaf(p0, aa.x, s_lo);
                        s_lo = fmaf(p1, aa.y, s_lo);
                        s_hi = fmaf(p2, aa.x, s_hi);
                        s_hi = fmaf(p3, aa.y, s_hi);
                    }
                    s_lo += __shfl_xor_sync(0xffffffffu, s_lo, 1);
                    s_lo += __shfl_xor_sync(0xffffffffu, s_lo, 2);
                    s_hi += __shfl_xor_sync(0xffffffffu, s_hi, 1);
                    s_hi += __shfl_xor_sync(0xffffffffu, s_hi, 2);
                    if (qid == 0) {
                        sm->Sc2[h][klo][wcol] = s_lo;
                        sm->Sc2[h][khi][wcol] = s_hi;
                    }
                }
            }
            // pair-local sync: both warps of node h (64 threads)
            bar_sync(BAR_PAIR + h, 64);

            // ---- softmax over k + 21-bin logits + log_softmax (even warp) ----
            if (wcol == 0) {
                const int n = tile * 4 + h;
                const float aA = tb->Am[h][lane];
                const int   sk = tb->Sv[h][lane];

                float score = sm->Sc2[h][lane][0] + sm->Sc2[h][lane][1];
                float mx = score;
                #pragma unroll
                for (int o = 16; o > 0; o >>= 1)
                    mx = fmaxf(mx, __shfl_xor_sync(0xffffffffu, mx, o));
                float e = expf(score - mx);
                float ssum = e;
                #pragma unroll
                for (int o = 16; o > 0; o >>= 1)
                    ssum += __shfl_xor_sync(0xffffffffu, ssum, o);
                atomicAdd(&tb->Wv[h][sk], (e / ssum) * aA);
                __syncwarp();

                float lg = -1e30f;
                if (lane < VV) {
                    lg = sm->G0[lane] + tb->Mk[h] * sm->G1[lane];
                    #pragma unroll
                    for (int u = 0; u < VV; u++)
                        lg = fmaf(tb->Wv[h][u], sm->TW[u][lane], lg);
                }
                float mx2 = lg;
                #pragma unroll
                for (int o = 16; o > 0; o >>= 1)
                    mx2 = fmaxf(mx2, __shfl_xor_sync(0xffffffffu, mx2, o));
                float e2 = (lane < VV) ? expf(lg - mx2) : 0.f;
                float s2 = e2;
                #pragma unroll
                for (int o = 16; o > 0; o >>= 1)
                    s2 += __shfl_xor_sync(0xffffffffu, s2, o);
                if (lane < VV)
                    out[n * VV + lane] = lg - mx2 - logf(s2);
            }
            bar_arrive(BAR_EMPTY + p, 320);
        }
    } else {
        // =========================== PRODUCERS ===========================
        const int tp = t - 256;                     // 0..63
        for (int it = 0; it < niter; it++) {
            const int tile = b + it * GRID;
            const int p = it & 1;
            if (it >= 2) bar_sync(BAR_EMPTY + p, 320);
            TileBuf* tb = &sm->buf[p];

            const float4* Eg = (const float4*)(E + (size_t)tile * (CC * CC));
            char* Ab = (char*)tb->A;
            // rows 0-63 (s = 0..31)
            #pragma unroll 16
            for (int s = 0; s < 32; s++) {
                const int i = tp + (s << 6);
                float4 v = Eg[i];
                const int r = i >> 5, q = i & 31;
                __nv_bfloat162 lo = __float22bfloat162_rn(make_float2(v.x, v.y));
                __nv_bfloat162 hi = __float22bfloat162_rn(make_float2(v.z, v.w));
                uint2 pk;
                pk.x = *(const uint32_t*)&lo;
                pk.y = *(const uint32_t*)&hi;
                *(uint2*)(Ab + r * 256 + (((q >> 1) ^ (r & 7)) << 4) + (q & 1) * 8) = pk;
            }
            bar_arrive(BAR_HALF + p, 192);          // nodes 0-1 may start
            // rows 64-127 (s = 32..63)
            #pragma unroll 16
            for (int s = 32; s < 64; s++) {
                const int i = tp + (s << 6);
                float4 v = Eg[i];
                const int r = i >> 5, q = i & 31;
                __nv_bfloat162 lo = __float22bfloat162_rn(make_float2(v.x, v.y));
                __nv_bfloat162 hi = __float22bfloat162_rn(make_float2(v.z, v.w));
                uint2 pk;
                pk.x = *(const uint32_t*)&lo;
                pk.y = *(const uint32_t*)&hi;
                *(uint2*)(Ab + r * 256 + (((q >> 1) ^ (r & 7)) << 4) + (q & 1) * 8) = pk;
            }
            // metadata
            #pragma unroll
            for (int i = tp; i < 128; i += 64) {
                const int hh = i >> 5, k = i & 31;
                const int n = tile * 4 + hh;
                const int j = E_idx[n * KK + k];
                tb->Sv[hh][k] = S[j];
                float kn = g_key[n], kj = g_key[j];
                float att = (kn > kj || (kn == kj && n > j)) ? 1.f : 0.f;
                tb->Am[hh][k] = mask[n] * att;
            }
            if (tp < 4) tb->Mk[tp] = mask[tile * 4 + tp];
            for (int i = tp; i < 4 * VV; i += 64) tb->Wv[i / VV][i % VV] = 0.f;

            bar_arrive(BAR_FULL + p, 320);
        }
    }
}

// ---------------- launch ----------------
extern "C" void kernel_launch(void* const* d_in, const int* in_sizes, int n_in,
                              void* d_out, int out_size)
{
    const float* E       = (const float*)d_in[0];
    const int*   E_idx   = (const int*)  d_in[1];
    const int*   S       = (const int*)  d_in[2];
    const float* mask    = (const float*)d_in[3];
    const float* chain_M = (const float*)d_in[4];
    const float* z       = (const float*)d_in[5];
    const float* bl1     = (const float*)d_in[7];
    const float* bo1     = (const float*)d_in[13];
    const float* Wl2     = (const float*)d_in[14];
    const float* bl2     = (const float*)d_in[15];
    const float* Wr2     = (const float*)d_in[16];
    const float* br2     = (const float*)d_in[17];
    const float* We2     = (const float*)d_in[18];
    const float* be2     = (const float*)d_in[19];
    const float* a2      = (const float*)d_in[20];
    const float* bo2     = (const float*)d_in[21];
    const float* W_s     = (const float*)d_in[22];
    const float* W_out   = (const float*)d_in[23];
    const float* b_out   = (const float*)d_in[24];

    float* out = (float*)d_out;

    const int smem_bytes = (int)sizeof(Smem);
    cudaFuncSetAttribute(gat_mma_kernel,
                         cudaFuncAttributeMaxDynamicSharedMemorySize, smem_bytes);

    precompute_kernel<<<32, 256>>>(bl1, bo1, Wl2, bl2, Wr2, br2, be2, bo2, We2,
                                   W_s, W_out, b_out, mask, chain_M, z);
    gat_mma_kernel<<<GRID, 320, smem_bytes>>>(E, E_idx, S, mask, a2, out);
}